// round 1
// baseline (speedup 1.0000x reference)
#include <cuda_runtime.h>

// Transducer KD loss prep.
// Shapes: logits/teacher (N=8, T=200, U=50, V=500) fp32; y (N,U) i32;
// x_lens (N,) i32; y_lens (N,) i32. Output (2, N, T, U, 3) fp32.
//
// One warp per (s, n, t, u) row (s=0: student logits, s=1: teacher).
// Row = 500 fp32 = 125 float4, warp-coalesced. Masked rows skip the read.

#define TN 8
#define TT 200
#define TU 50
#define TV 500
#define T_EPS 1e-10f

__global__ void __launch_bounds__(256, 8)
transducer_kd_kernel(const float* __restrict__ logits,
                     const float* __restrict__ teacher,
                     const int*   __restrict__ y,
                     const int*   __restrict__ x_lens,
                     const int*   __restrict__ y_lens,
                     float*       __restrict__ out)
{
    const int warp_global = (int)((blockIdx.x * blockDim.x + threadIdx.x) >> 5);
    const int lane = threadIdx.x & 31;

    const int ROWS_PER_TENSOR = TN * TT * TU;          // 80000
    const int TOTAL = 2 * ROWS_PER_TENSOR;             // 160000
    if (warp_global >= TOTAL) return;

    const int s = warp_global / ROWS_PER_TENSOR;       // 0 = student, 1 = teacher
    const int r = warp_global - s * ROWS_PER_TENSOR;   // row within tensor
    const int n  = r / (TT * TU);
    const int tu = r - n * (TT * TU);
    const int t  = tu / TU;
    const int u  = tu - t * TU;

    float* o = out + (size_t)warp_global * 3;

    // Mask first — skip the 2000B row read entirely for masked positions.
    const bool active = (t < x_lens[n]) && (u < y_lens[n]);
    if (!active) {
        if (lane < 3) o[lane] = 0.0f;
        return;
    }

    const float* base = (s == 0 ? logits : teacher) + (size_t)r * TV;
    const float4* b4 = (const float4*)base;

    // Sum of exp over V=500 (125 float4). Lanes 0..28 do 4 iters, 29..31 do 3.
    float acc = 0.0f;
    #pragma unroll 4
    for (int i = lane; i < TV / 4; i += 32) {
        float4 v = b4[i];
        acc += __expf(v.x) + __expf(v.y) + __expf(v.z) + __expf(v.w);
    }
    #pragma unroll
    for (int off = 16; off > 0; off >>= 1)
        acc += __shfl_xor_sync(0xFFFFFFFFu, acc, off);

    if (lane == 0) {
        const int yi = y[n * TU + u];
        const float inv = 1.0f / acc;
        const float py    = __expf(base[yi]) * inv;
        const float blank = __expf(base[0])  * inv;
        const float rem   = 1.0f - py - blank;
        if (s == 0) {
            // student: log(clip(x, EPS, 1))
            float a0 = fminf(fmaxf(py,    T_EPS), 1.0f);
            float a1 = fminf(fmaxf(blank, T_EPS), 1.0f);
            float a2 = fminf(fmaxf(rem,   T_EPS), 1.0f);
            o[0] = logf(a0);
            o[1] = logf(a1);
            o[2] = logf(a2);
        } else {
            // teacher: raw probs; rem clamped to EPS if negative
            o[0] = py;
            o[1] = blank;
            o[2] = (rem < 0.0f) ? T_EPS : rem;
        }
    }
}

extern "C" void kernel_launch(void* const* d_in, const int* in_sizes, int n_in,
                              void* d_out, int out_size)
{
    const float* logits  = (const float*)d_in[0];
    const float* teacher = (const float*)d_in[1];
    const int*   y       = (const int*)d_in[2];
    const int*   x_lens  = (const int*)d_in[3];
    const int*   y_lens  = (const int*)d_in[4];
    float* out = (float*)d_out;

    const int TOTAL_WARPS = 2 * TN * TT * TU;   // 160000
    const int WARPS_PER_BLOCK = 8;              // 256 threads
    const int blocks = (TOTAL_WARPS + WARPS_PER_BLOCK - 1) / WARPS_PER_BLOCK;
    transducer_kd_kernel<<<blocks, WARPS_PER_BLOCK * 32>>>(
        logits, teacher, y, x_lens, y_lens, out);
}

// round 2
// speedup vs baseline: 1.3003x; 1.3003x over previous
#include <cuda_runtime.h>

// Transducer KD loss prep.
// Shapes: logits/teacher (N=8, T=200, U=50, V=500) fp32; y (N,U) i32;
// x_lens (N,) i32; y_lens (N,) i32. Output (2, N, T, U, 3) fp32.
//
// One warp per (s, n, t, u) row. Row = 500 fp32 = 125 float4.
// Masked rows (44%) skip the 2000B read entirely.
// Loads are front-batched (4 LDG.128 per lane, last predicated) to maximize
// per-warp MLP; exp/sum happens after all loads are in flight.

#define TN 8
#define TT 200
#define TU 50
#define TV 500
#define T_EPS 1e-10f
#define NEG_BIG -1e30f

__global__ void __launch_bounds__(256, 8)
transducer_kd_kernel(const float* __restrict__ logits,
                     const float* __restrict__ teacher,
                     const int*   __restrict__ y,
                     const int*   __restrict__ x_lens,
                     const int*   __restrict__ y_lens,
                     float*       __restrict__ out)
{
    const int warp_global = (int)((blockIdx.x * blockDim.x + threadIdx.x) >> 5);
    const int lane = threadIdx.x & 31;

    const int ROWS_PER_TENSOR = TN * TT * TU;          // 80000
    const int TOTAL = 2 * ROWS_PER_TENSOR;             // 160000
    if (warp_global >= TOTAL) return;

    const int s = warp_global / ROWS_PER_TENSOR;       // 0 = student, 1 = teacher
    const int r = warp_global - s * ROWS_PER_TENSOR;   // row within tensor
    const int n  = r / (TT * TU);
    const int tu = r - n * (TT * TU);
    const int t  = tu / TU;
    const int u  = tu - t * TU;

    float* o = out + (size_t)warp_global * 3;

    // Mask first — skip the row read entirely for masked positions.
    const bool active = (t < x_lens[n]) && (u < y_lens[n]);
    if (!active) {
        if (lane < 3) o[lane] = 0.0f;
        return;
    }

    const float* base = (s == 0 ? logits : teacher) + (size_t)r * TV;
    const float4* b4 = (const float4*)base;

    // ---- Phase 1: front-batched loads (max MLP). 125 float4 per row. ----
    float4 v0 = b4[lane];
    float4 v1 = b4[lane + 32];
    float4 v2 = b4[lane + 64];
    float4 v3 = make_float4(NEG_BIG, NEG_BIG, NEG_BIG, NEG_BIG);
    if (lane < 29) v3 = b4[lane + 96];   // indices 96..124

    // Fetch the gather index early too (lane 0 will use it).
    const int yi = y[n * TU + u];

    // ---- Phase 2: exp + tree sum ----
    float a0 = __expf(v0.x) + __expf(v0.y) + __expf(v0.z) + __expf(v0.w);
    float a1 = __expf(v1.x) + __expf(v1.y) + __expf(v1.z) + __expf(v1.w);
    float a2 = __expf(v2.x) + __expf(v2.y) + __expf(v2.z) + __expf(v2.w);
    float a3 = __expf(v3.x) + __expf(v3.y) + __expf(v3.z) + __expf(v3.w);
    float acc = (a0 + a1) + (a2 + a3);

    #pragma unroll
    for (int off = 16; off > 0; off >>= 1)
        acc += __shfl_xor_sync(0xFFFFFFFFu, acc, off);

    if (lane == 0) {
        const float inv = 1.0f / acc;
        const float py    = __expf(base[yi]) * inv;
        const float blank = __expf(base[0])  * inv;
        const float rem   = 1.0f - py - blank;
        if (s == 0) {
            // student: log(clip(x, EPS, 1))
            float c0 = fminf(fmaxf(py,    T_EPS), 1.0f);
            float c1 = fminf(fmaxf(blank, T_EPS), 1.0f);
            float c2 = fminf(fmaxf(rem,   T_EPS), 1.0f);
            o[0] = logf(c0);
            o[1] = logf(c1);
            o[2] = logf(c2);
        } else {
            // teacher: raw probs; rem clamped to EPS if negative
            o[0] = py;
            o[1] = blank;
            o[2] = (rem < 0.0f) ? T_EPS : rem;
        }
    }
}

extern "C" void kernel_launch(void* const* d_in, const int* in_sizes, int n_in,
                              void* d_out, int out_size)
{
    const float* logits  = (const float*)d_in[0];
    const float* teacher = (const float*)d_in[1];
    const int*   y       = (const int*)d_in[2];
    const int*   x_lens  = (const int*)d_in[3];
    const int*   y_lens  = (const int*)d_in[4];
    float* out = (float*)d_out;

    const int TOTAL_WARPS = 2 * TN * TT * TU;   // 160000
    const int WARPS_PER_BLOCK = 8;              // 256 threads
    const int blocks = (TOTAL_WARPS + WARPS_PER_BLOCK - 1) / WARPS_PER_BLOCK;
    transducer_kd_kernel<<<blocks, WARPS_PER_BLOCK * 32>>>(
        logits, teacher, y, x_lens, y_lens, out);
}

// round 3
// speedup vs baseline: 1.3634x; 1.0485x over previous
#include <cuda_runtime.h>

// Transducer KD loss prep.
// logits/teacher (N=8,T=200,U=50,V=500) fp32; y (N,U) i32; x_lens,y_lens (N,) i32.
// Output (2, N, T, U, 3) fp32.
//
// One warp per (n,t,u) position, processing BOTH the student and teacher row
// (they share mask + y index). 8 front-batched LDG.128 per lane (MLP_p1=8),
// streaming (.cs) since there is zero reuse. py/blank logits are extracted
// from registers via shfl — no reload.

#define TN 8
#define TT 200
#define TU 50
#define TV 500
#define T_EPS 1e-10f
#define NEG_BIG -1e30f

__global__ void __launch_bounds__(256)
transducer_kd_kernel(const float* __restrict__ logits,
                     const float* __restrict__ teacher,
                     const int*   __restrict__ y,
                     const int*   __restrict__ x_lens,
                     const int*   __restrict__ y_lens,
                     float*       __restrict__ out)
{
    const int warp_global = (int)((blockIdx.x * blockDim.x + threadIdx.x) >> 5);
    const int lane = threadIdx.x & 31;

    const int ROWS = TN * TT * TU;            // 80000 positions
    if (warp_global >= ROWS) return;

    const int r  = warp_global;
    const int n  = r / (TT * TU);
    const int tu = r - n * (TT * TU);
    const int t  = tu / TU;
    const int u  = tu - t * TU;

    float* os = out + (size_t)r * 3;                    // student triple
    float* ot = out + (size_t)(ROWS + r) * 3;           // teacher triple

    const bool active = (t < x_lens[n]) && (u < y_lens[n]);
    if (!active) {
        if (lane < 3) { os[lane] = 0.0f; ot[lane] = 0.0f; }
        return;
    }

    const float4* s4 = (const float4*)(logits  + (size_t)r * TV);
    const float4* t4 = (const float4*)(teacher + (size_t)r * TV);
    const bool tail = (lane < 29);            // 125 float4 per row

    // ---- Phase 1: 8 front-batched streaming loads ----
    float4 sv0 = __ldcs(s4 + lane);
    float4 sv1 = __ldcs(s4 + lane + 32);
    float4 sv2 = __ldcs(s4 + lane + 64);
    float4 tv0 = __ldcs(t4 + lane);
    float4 tv1 = __ldcs(t4 + lane + 32);
    float4 tv2 = __ldcs(t4 + lane + 64);
    float4 sv3 = make_float4(NEG_BIG, NEG_BIG, NEG_BIG, NEG_BIG);
    float4 tv3 = make_float4(NEG_BIG, NEG_BIG, NEG_BIG, NEG_BIG);
    if (tail) {
        sv3 = __ldcs(s4 + lane + 96);
        tv3 = __ldcs(t4 + lane + 96);
    }
    const int yi = __ldg(y + n * TU + u);     // uniform across warp

    // ---- Extract py / blank raw logits from registers (no reload) ----
    const int idx4 = yi >> 2;                 // which float4 (0..124)
    const int comp = yi & 3;
    const int src  = idx4 & 31;
    const int grp  = idx4 >> 5;               // 0..3

    float4 svy = (grp == 0) ? sv0 : (grp == 1) ? sv1 : (grp == 2) ? sv2 : sv3;
    float4 tvy = (grp == 0) ? tv0 : (grp == 1) ? tv1 : (grp == 2) ? tv2 : tv3;
    float sx = (comp == 0) ? svy.x : (comp == 1) ? svy.y : (comp == 2) ? svy.z : svy.w;
    float tx = (comp == 0) ? tvy.x : (comp == 1) ? tvy.y : (comp == 2) ? tvy.z : tvy.w;
    const float s_logit_y = __shfl_sync(0xFFFFFFFFu, sx, src);
    const float t_logit_y = __shfl_sync(0xFFFFFFFFu, tx, src);
    const float s_logit_b = __shfl_sync(0xFFFFFFFFu, sv0.x, 0);
    const float t_logit_b = __shfl_sync(0xFFFFFFFFu, tv0.x, 0);

    // ---- Phase 2: exp + tree sums (both rows) ----
    float sa = (__expf(sv0.x) + __expf(sv0.y)) + (__expf(sv0.z) + __expf(sv0.w));
    sa += (__expf(sv1.x) + __expf(sv1.y)) + (__expf(sv1.z) + __expf(sv1.w));
    sa += (__expf(sv2.x) + __expf(sv2.y)) + (__expf(sv2.z) + __expf(sv2.w));
    sa += (__expf(sv3.x) + __expf(sv3.y)) + (__expf(sv3.z) + __expf(sv3.w));
    float ta = (__expf(tv0.x) + __expf(tv0.y)) + (__expf(tv0.z) + __expf(tv0.w));
    ta += (__expf(tv1.x) + __expf(tv1.y)) + (__expf(tv1.z) + __expf(tv1.w));
    ta += (__expf(tv2.x) + __expf(tv2.y)) + (__expf(tv2.z) + __expf(tv2.w));
    ta += (__expf(tv3.x) + __expf(tv3.y)) + (__expf(tv3.z) + __expf(tv3.w));

    #pragma unroll
    for (int off = 16; off > 0; off >>= 1) {
        sa += __shfl_xor_sync(0xFFFFFFFFu, sa, off);
        ta += __shfl_xor_sync(0xFFFFFFFFu, ta, off);
    }

    if (lane == 0) {
        // student: log(clip(x, EPS, 1))
        const float sinv   = 1.0f / sa;
        const float spy    = __expf(s_logit_y) * sinv;
        const float sblank = __expf(s_logit_b) * sinv;
        const float srem   = 1.0f - spy - sblank;
        os[0] = logf(fminf(fmaxf(spy,    T_EPS), 1.0f));
        os[1] = logf(fminf(fmaxf(sblank, T_EPS), 1.0f));
        os[2] = logf(fminf(fmaxf(srem,   T_EPS), 1.0f));
        // teacher: raw probs; rem clamped to EPS if negative
        const float tinv   = 1.0f / ta;
        const float tpy    = __expf(t_logit_y) * tinv;
        const float tblank = __expf(t_logit_b) * tinv;
        const float trem   = 1.0f - tpy - tblank;
        ot[0] = tpy;
        ot[1] = tblank;
        ot[2] = (trem < 0.0f) ? T_EPS : trem;
    }
}

extern "C" void kernel_launch(void* const* d_in, const int* in_sizes, int n_in,
                              void* d_out, int out_size)
{
    const float* logits  = (const float*)d_in[0];
    const float* teacher = (const float*)d_in[1];
    const int*   y       = (const int*)d_in[2];
    const int*   x_lens  = (const int*)d_in[3];
    const int*   y_lens  = (const int*)d_in[4];
    float* out = (float*)d_out;

    const int TOTAL_WARPS = TN * TT * TU;   // 80000
    const int WARPS_PER_BLOCK = 8;          // 256 threads
    const int blocks = (TOTAL_WARPS + WARPS_PER_BLOCK - 1) / WARPS_PER_BLOCK;
    transducer_kd_kernel<<<blocks, WARPS_PER_BLOCK * 32>>>(
        logits, teacher, y, x_lens, y_lens, out);
}

// round 4
// speedup vs baseline: 1.3918x; 1.0209x over previous
#include <cuda_runtime.h>

// Transducer KD loss prep.
// logits/teacher (N=8,T=200,U=50,V=500) fp32; y (N,U) i32; x_lens,y_lens (N,) i32.
// Output (2, N, T, U, 3) fp32.
//
// One warp per (n,t,u) position, processing BOTH student and teacher rows
// (shared mask + y index). 8 front-batched LDG.128.cs per lane (MLP_p1=8).
// Lane 0 re-fetches the 4 gathered logits via __ldg (L2 hit) instead of a
// register shuffle-extract — saves ~10 regs, restoring occupancy.

#define TN 8
#define TT 200
#define TU 50
#define TV 500
#define T_EPS 1e-10f
#define NEG_BIG -1e30f

__global__ void __launch_bounds__(128)
transducer_kd_kernel(const float* __restrict__ logits,
                     const float* __restrict__ teacher,
                     const int*   __restrict__ y,
                     const int*   __restrict__ x_lens,
                     const int*   __restrict__ y_lens,
                     float*       __restrict__ out)
{
    const int warp_global = (int)((blockIdx.x * blockDim.x + threadIdx.x) >> 5);
    const int lane = threadIdx.x & 31;

    const int ROWS = TN * TT * TU;            // 80000 positions
    if (warp_global >= ROWS) return;

    const int r  = warp_global;
    const int n  = r / (TT * TU);
    const int tu = r - n * (TT * TU);
    const int t  = tu / TU;
    const int u  = tu - t * TU;

    float* os = out + (size_t)r * 3;                    // student triple
    float* ot = out + (size_t)(ROWS + r) * 3;           // teacher triple

    const bool active = (t < x_lens[n]) && (u < y_lens[n]);
    if (!active) {
        if (lane < 3) { os[lane] = 0.0f; ot[lane] = 0.0f; }
        return;
    }

    const float* sbase = logits  + (size_t)r * TV;
    const float* tbase = teacher + (size_t)r * TV;
    const float4* s4 = (const float4*)sbase;
    const float4* t4 = (const float4*)tbase;
    const bool tail = (lane < 29);            // 125 float4 per row

    // ---- Phase 1: 8 front-batched streaming loads ----
    float4 sv0 = __ldcs(s4 + lane);
    float4 sv1 = __ldcs(s4 + lane + 32);
    float4 sv2 = __ldcs(s4 + lane + 64);
    float4 tv0 = __ldcs(t4 + lane);
    float4 tv1 = __ldcs(t4 + lane + 32);
    float4 tv2 = __ldcs(t4 + lane + 64);
    float4 sv3 = make_float4(NEG_BIG, NEG_BIG, NEG_BIG, NEG_BIG);
    float4 tv3 = make_float4(NEG_BIG, NEG_BIG, NEG_BIG, NEG_BIG);
    if (tail) {
        sv3 = __ldcs(s4 + lane + 96);
        tv3 = __ldcs(t4 + lane + 96);
    }

    // ---- Phase 2: exp + tree sums (both rows) ----
    float sa = (__expf(sv0.x) + __expf(sv0.y)) + (__expf(sv0.z) + __expf(sv0.w));
    sa += (__expf(sv1.x) + __expf(sv1.y)) + (__expf(sv1.z) + __expf(sv1.w));
    sa += (__expf(sv2.x) + __expf(sv2.y)) + (__expf(sv2.z) + __expf(sv2.w));
    sa += (__expf(sv3.x) + __expf(sv3.y)) + (__expf(sv3.z) + __expf(sv3.w));
    float ta = (__expf(tv0.x) + __expf(tv0.y)) + (__expf(tv0.z) + __expf(tv0.w));
    ta += (__expf(tv1.x) + __expf(tv1.y)) + (__expf(tv1.z) + __expf(tv1.w));
    ta += (__expf(tv2.x) + __expf(tv2.y)) + (__expf(tv2.z) + __expf(tv2.w));
    ta += (__expf(tv3.x) + __expf(tv3.y)) + (__expf(tv3.z) + __expf(tv3.w));

    #pragma unroll
    for (int off = 16; off > 0; off >>= 1) {
        sa += __shfl_xor_sync(0xFFFFFFFFu, sa, off);
        ta += __shfl_xor_sync(0xFFFFFFFFu, ta, off);
    }

    if (lane == 0) {
        const int yi = __ldg(y + n * TU + u);
        // gathered logits: re-fetch from L2 (rows just streamed through it)
        const float s_ly = __ldg(sbase + yi);
        const float t_ly = __ldg(tbase + yi);
        const float s_lb = __ldg(sbase);
        const float t_lb = __ldg(tbase);

        // student: log(clip(x, EPS, 1))
        const float sinv   = 1.0f / sa;
        const float spy    = __expf(s_ly) * sinv;
        const float sblank = __expf(s_lb) * sinv;
        const float srem   = 1.0f - spy - sblank;
        os[0] = logf(fminf(fmaxf(spy,    T_EPS), 1.0f));
        os[1] = logf(fminf(fmaxf(sblank, T_EPS), 1.0f));
        os[2] = logf(fminf(fmaxf(srem,   T_EPS), 1.0f));
        // teacher: raw probs; rem clamped to EPS if negative
        const float tinv   = 1.0f / ta;
        const float tpy    = __expf(t_ly) * tinv;
        const float tblank = __expf(t_lb) * tinv;
        const float trem   = 1.0f - tpy - tblank;
        ot[0] = tpy;
        ot[1] = tblank;
        ot[2] = (trem < 0.0f) ? T_EPS : trem;
    }
}

extern "C" void kernel_launch(void* const* d_in, const int* in_sizes, int n_in,
                              void* d_out, int out_size)
{
    const float* logits  = (const float*)d_in[0];
    const float* teacher = (const float*)d_in[1];
    const int*   y       = (const int*)d_in[2];
    const int*   x_lens  = (const int*)d_in[3];
    const int*   y_lens  = (const int*)d_in[4];
    float* out = (float*)d_out;

    const int TOTAL_WARPS = TN * TT * TU;   // 80000
    const int WARPS_PER_BLOCK = 4;          // 128 threads
    const int blocks = (TOTAL_WARPS + WARPS_PER_BLOCK - 1) / WARPS_PER_BLOCK;
    transducer_kd_kernel<<<blocks, WARPS_PER_BLOCK * 32>>>(
        logits, teacher, y, x_lens, y_lens, out);
}